// round 3
// baseline (speedup 1.0000x reference)
#include <cuda_runtime.h>
#include <cstdint>

// ---------------------------------------------------------------------------
// FPNAttentionV2: 7x conv1x1 (C=256) + 1x conv3x3/s2, all outputs in BHWC.
// TF32 mma.sync tiled GEMM. out[p,o] = sum_c X[c,p] * W[o,c] + b[o]
// CTA tile: 128 pixels x 64 outch, BK=32. 8 warps (4 x 2), warp tile 32x32.
// ---------------------------------------------------------------------------

#define CC 256

__device__ __forceinline__ uint32_t f2tf32(float f) {
    uint32_t r;
    asm("cvt.rna.tf32.f32 %0, %1;" : "=r"(r) : "f"(f));
    return r;
}

__device__ __forceinline__ void mma_tf32(float* c, const uint32_t* a, const uint32_t* b) {
    asm volatile(
        "mma.sync.aligned.m16n8k8.row.col.f32.tf32.tf32.f32 "
        "{%0,%1,%2,%3}, {%4,%5,%6,%7}, {%8,%9}, {%0,%1,%2,%3};"
        : "+f"(c[0]), "+f"(c[1]), "+f"(c[2]), "+f"(c[3])
        : "r"(a[0]), "r"(a[1]), "r"(a[2]), "r"(a[3]), "r"(b[0]), "r"(b[1]));
}

// Shared tiles: Xs[k][p] stride 136 (8 mod 32 -> conflict-free frag LDS),
// Ws[k][o] stride 72.
struct SmemTiles {
    uint32_t Xs[32][136];
    uint32_t Ws[32][72];
};

// UPSAMPLE=1: input is 64x64 grid, each output pixel written to 2x2 block of
// a 128x128 BHWC output.
template <int UPSAMPLE>
__global__ __launch_bounds__(256) void conv1x1_kernel(
    const float* __restrict__ x, const float* __restrict__ w,
    const float* __restrict__ bias, float* __restrict__ out, int HW) {
    __shared__ SmemTiles s;

    const int tid  = threadIdx.x;
    const int lane = tid & 31;
    const int warp = tid >> 5;
    const int wm = warp & 3;   // 0..3  (M direction, 32 pixels each)
    const int wn = warp >> 2;  // 0..1  (N direction, 32 outch each)
    const int tg = lane & 3;   // thread-in-group
    const int gp = lane >> 2;  // group

    const int pt = blockIdx.x * 128;
    const int ot = blockIdx.y * 64;
    const int bb = blockIdx.z;

    const float* xb = x + (size_t)bb * CC * HW;

    float acc[2][4][4];
#pragma unroll
    for (int mt = 0; mt < 2; ++mt)
#pragma unroll
        for (int nt = 0; nt < 4; ++nt)
#pragma unroll
            for (int i = 0; i < 4; ++i) acc[mt][nt][i] = 0.f;

    for (int kt = 0; kt < CC / 32; ++kt) {
        // ---- load X tile: 32 c-rows x 128 pixels, float4 + STS.128 ----
#pragma unroll
        for (int l = 0; l < 4; ++l) {
            int k = warp + l * 8;
            float4 v = *reinterpret_cast<const float4*>(
                xb + (size_t)(kt * 32 + k) * HW + pt + (lane << 2));
            uint4 t;
            t.x = f2tf32(v.x); t.y = f2tf32(v.y);
            t.z = f2tf32(v.z); t.w = f2tf32(v.w);
            *reinterpret_cast<uint4*>(&s.Xs[k][lane << 2]) = t;
        }
        // ---- load W tile: 64 o-rows x 32 c, transpose into Ws[c][o] ----
#pragma unroll
        for (int l = 0; l < 2; ++l) {
            int idx = l * 256 + tid;
            int o = idx >> 3;
            int c4 = (idx & 7) << 2;
            float4 v = *reinterpret_cast<const float4*>(
                w + (size_t)(ot + o) * CC + kt * 32 + c4);
            s.Ws[c4 + 0][o] = f2tf32(v.x);
            s.Ws[c4 + 1][o] = f2tf32(v.y);
            s.Ws[c4 + 2][o] = f2tf32(v.z);
            s.Ws[c4 + 3][o] = f2tf32(v.w);
        }
        __syncthreads();

#pragma unroll
        for (int kk = 0; kk < 32; kk += 8) {
            uint32_t a[2][4];
#pragma unroll
            for (int mt = 0; mt < 2; ++mt) {
                int row = wm * 32 + mt * 16 + gp;
                a[mt][0] = s.Xs[kk + tg][row];
                a[mt][1] = s.Xs[kk + tg][row + 8];
                a[mt][2] = s.Xs[kk + tg + 4][row];
                a[mt][3] = s.Xs[kk + tg + 4][row + 8];
            }
            uint32_t bq[4][2];
#pragma unroll
            for (int nt = 0; nt < 4; ++nt) {
                int col = wn * 32 + nt * 8 + gp;
                bq[nt][0] = s.Ws[kk + tg][col];
                bq[nt][1] = s.Ws[kk + tg + 4][col];
            }
#pragma unroll
            for (int mt = 0; mt < 2; ++mt)
#pragma unroll
                for (int nt = 0; nt < 4; ++nt) mma_tf32(acc[mt][nt], a[mt], bq[nt]);
        }
        __syncthreads();
    }

    // ---- epilogue: bias + BHWC store ----
#pragma unroll
    for (int nt = 0; nt < 4; ++nt) {
        int o = ot + wn * 32 + nt * 8 + tg * 2;
        float b0 = __ldg(&bias[o]);
        float b1 = __ldg(&bias[o + 1]);
#pragma unroll
        for (int mt = 0; mt < 2; ++mt) {
#pragma unroll
            for (int half = 0; half < 2; ++half) {
                int pl = wm * 32 + mt * 16 + gp + half * 8;
                int pg = pt + pl;
                float2 r;
                r.x = acc[mt][nt][half * 2 + 0] + b0;
                r.y = acc[mt][nt][half * 2 + 1] + b1;
                if (UPSAMPLE) {
                    // conv grid is 64x64; fan out to 2x2 in 128x128 output
                    int h = pg >> 6, wcol = pg & 63;
                    float* base = out +
                        ((size_t)bb * 16384 + (size_t)(2 * h) * 128 + 2 * wcol) * CC + o;
                    *reinterpret_cast<float2*>(base) = r;
                    *reinterpret_cast<float2*>(base + CC) = r;
                    *reinterpret_cast<float2*>(base + 128 * CC) = r;
                    *reinterpret_cast<float2*>(base + 128 * CC + CC) = r;
                } else {
                    *reinterpret_cast<float2*>(out + ((size_t)bb * HW + pg) * CC + o) = r;
                }
            }
        }
    }
}

// 3x3 stride-2 pad-1 conv as 9 accumulated GEMMs (im2col on the fly).
// Output 64x64 per batch. CTA: 128 output pixels (2 rows) x 64 outch.
__global__ __launch_bounds__(256) void conv3x3s2_kernel(
    const float* __restrict__ x, const float* __restrict__ w,
    const float* __restrict__ bias, float* __restrict__ out) {
    __shared__ SmemTiles s;

    const int tid  = threadIdx.x;
    const int lane = tid & 31;
    const int warp = tid >> 5;
    const int wm = warp & 3;
    const int wn = warp >> 2;
    const int tg = lane & 3;
    const int gp = lane >> 2;

    const int pt = blockIdx.x * 128;     // output pixel tile (64x64 grid)
    const int oh0 = pt >> 6;             // first output row of tile
    const int ot = blockIdx.y * 64;
    const int bb = blockIdx.z;

    const float* xb = x + (size_t)bb * CC * 16384;

    float acc[2][4][4];
#pragma unroll
    for (int mt = 0; mt < 2; ++mt)
#pragma unroll
        for (int nt = 0; nt < 4; ++nt)
#pragma unroll
            for (int i = 0; i < 4; ++i) acc[mt][nt][i] = 0.f;

    for (int kt = 0; kt < CC / 32; ++kt) {
        for (int tap = 0; tap < 9; ++tap) {
            int ti = tap / 3, tj = tap % 3;
            // ---- X tile: gather strided input with zero-pad ----
#pragma unroll
            for (int l = 0; l < 16; ++l) {
                int idx = l * 256 + tid;
                int cl = idx >> 7;    // 0..31
                int p = idx & 127;
                int r = p >> 6, wc = p & 63;
                int ih = 2 * (oh0 + r) - 1 + ti;
                int iw = 2 * wc - 1 + tj;
                float v = 0.f;
                if (ih >= 0 && iw >= 0)
                    v = xb[(size_t)(kt * 32 + cl) * 16384 + ih * 128 + iw];
                s.Xs[cl][p] = f2tf32(v);
            }
            // ---- W tile: w[o][c][ti][tj] ----
#pragma unroll
            for (int l = 0; l < 8; ++l) {
                int idx = l * 256 + tid;
                int o = idx >> 5, cl = idx & 31;
                float v = w[((size_t)(ot + o) * CC + kt * 32 + cl) * 9 + ti * 3 + tj];
                s.Ws[cl][o] = f2tf32(v);
            }
            __syncthreads();

#pragma unroll
            for (int kk = 0; kk < 32; kk += 8) {
                uint32_t a[2][4];
#pragma unroll
                for (int mt = 0; mt < 2; ++mt) {
                    int row = wm * 32 + mt * 16 + gp;
                    a[mt][0] = s.Xs[kk + tg][row];
                    a[mt][1] = s.Xs[kk + tg][row + 8];
                    a[mt][2] = s.Xs[kk + tg + 4][row];
                    a[mt][3] = s.Xs[kk + tg + 4][row + 8];
                }
                uint32_t bq[4][2];
#pragma unroll
                for (int nt = 0; nt < 4; ++nt) {
                    int col = wn * 32 + nt * 8 + gp;
                    bq[nt][0] = s.Ws[kk + tg][col];
                    bq[nt][1] = s.Ws[kk + tg + 4][col];
                }
#pragma unroll
                for (int mt = 0; mt < 2; ++mt)
#pragma unroll
                    for (int nt = 0; nt < 4; ++nt) mma_tf32(acc[mt][nt], a[mt], bq[nt]);
            }
            __syncthreads();
        }
    }

#pragma unroll
    for (int nt = 0; nt < 4; ++nt) {
        int o = ot + wn * 32 + nt * 8 + tg * 2;
        float b0 = __ldg(&bias[o]);
        float b1 = __ldg(&bias[o + 1]);
#pragma unroll
        for (int mt = 0; mt < 2; ++mt) {
#pragma unroll
            for (int half = 0; half < 2; ++half) {
                int pl = wm * 32 + mt * 16 + gp + half * 8;
                int pg = pt + pl;
                float2 r;
                r.x = acc[mt][nt][half * 2 + 0] + b0;
                r.y = acc[mt][nt][half * 2 + 1] + b1;
                *reinterpret_cast<float2*>(out + ((size_t)bb * 4096 + pg) * CC + o) = r;
            }
        }
    }
}

extern "C" void kernel_launch(void* const* d_in, const int* in_sizes, int n_in,
                              void* d_out, int out_size) {
    const float* x1 = (const float*)d_in[0];
    const float* x2 = (const float*)d_in[1];
    const float* q1_w = (const float*)d_in[2];
    const float* q1_b = (const float*)d_in[3];
    const float* q2_w = (const float*)d_in[4];
    const float* q2_b = (const float*)d_in[5];
    const float* ks1_w = (const float*)d_in[6];
    const float* ks1_b = (const float*)d_in[7];
    const float* ks2_w = (const float*)d_in[8];
    const float* ks2_b = (const float*)d_in[9];
    const float* kup_w = (const float*)d_in[10];
    const float* kup_b = (const float*)d_in[11];
    const float* v1_w = (const float*)d_in[12];
    const float* v1_b = (const float*)d_in[13];
    const float* v2_w = (const float*)d_in[14];
    const float* v2_b = (const float*)d_in[15];
    const float* kd_w = (const float*)d_in[16];
    const float* kd_b = (const float*)d_in[17];

    float* out = (float*)d_out;
    // Output regions (element offsets), BHWC each.
    float* q1  = out;                    // 2*128*128*256
    float* q2  = out + 8388608;          // 2*64*64*256
    float* kup = out + 10485760;         // 2*128*128*256 (upsampled)
    float* ks1 = out + 18874368;         // 2*128*128*256
    float* ks2 = out + 27262976;         // 2*64*64*256
    float* kdn = out + 29360128;         // 2*64*64*256
    float* v1  = out + 31457280;         // 2*128*128*256
    float* v2  = out + 39845888;         // 2*64*64*256

    dim3 blk(256);
    dim3 g1(128, 4, 2);  // HW=16384: 128 pixel tiles x 4 outch tiles x B=2
    dim3 g2(32, 4, 2);   // HW=4096

    conv1x1_kernel<0><<<g1, blk>>>(x1, q1_w, q1_b, q1, 16384);
    conv1x1_kernel<0><<<g1, blk>>>(x1, ks1_w, ks1_b, ks1, 16384);
    conv1x1_kernel<0><<<g1, blk>>>(x1, v1_w, v1_b, v1, 16384);
    conv1x1_kernel<0><<<g2, blk>>>(x2, q2_w, q2_b, q2, 4096);
    conv1x1_kernel<0><<<g2, blk>>>(x2, ks2_w, ks2_b, ks2, 4096);
    conv1x1_kernel<0><<<g2, blk>>>(x2, v2_w, v2_b, v2, 4096);
    conv1x1_kernel<1><<<g2, blk>>>(x2, kup_w, kup_b, kup, 4096);
    conv3x3s2_kernel<<<g2, blk>>>(x1, kd_w, kd_b, kdn);
}

// round 4
// speedup vs baseline: 1.1760x; 1.1760x over previous
#include <cuda_runtime.h>
#include <cstdint>

// ---------------------------------------------------------------------------
// FPNAttentionV2: fused conv1x1 batches + conv3x3/s2, BHWC outputs.
// TF32 mma.sync m16n8k8. CTA tile 128 px x 128 och x BK=32.
// 8 warps arranged 4(M) x 2(N); warp tile 32 x 64 (mt=2, nt=8).
//
// Smem layout: tile[row][kperm], kperm(k) = (k%4)*8 + k/4, row stride 36
// words.  Thread (tg) reads its 8 k-words contiguously -> LDS.128,
// conflict-free (36*gp + 8*tg spans all 32 banks per phase).  X stores are
// conflict-free STS.128 along kperm.
// ---------------------------------------------------------------------------

#define CC 256
#define PAD 36

__device__ __forceinline__ uint32_t f2tf32(float f) {
    uint32_t r;
    asm("cvt.rna.tf32.f32 %0, %1;" : "=r"(r) : "f"(f));
    return r;
}

__device__ __forceinline__ void mma_tf32(float* c, const uint32_t* a, const uint32_t* b) {
    asm volatile(
        "mma.sync.aligned.m16n8k8.row.col.f32.tf32.tf32.f32 "
        "{%0,%1,%2,%3}, {%4,%5,%6,%7}, {%8,%9}, {%0,%1,%2,%3};"
        : "+f"(c[0]), "+f"(c[1]), "+f"(c[2]), "+f"(c[3])
        : "r"(a[0]), "r"(a[1]), "r"(a[2]), "r"(a[3]), "r"(b[0]), "r"(b[1]));
}

struct ConvSet {
    const float* w[4];
    const float* b[4];
    float* out[4];
};

// UPS: conv id whose output is 2x nearest-upsampled into a 2H x 2W BHWC
// tensor, or -1.  grid: (HW/128, nconv*2, B); blockIdx.y = conv*2 + ochHalf.
template <int UPS>
__global__ __launch_bounds__(256) void conv1x1_fused(
    const float* __restrict__ x, ConvSet cs, int HW) {
    __shared__ uint32_t Xs[128 * PAD];
    __shared__ uint32_t Ws[128 * PAD];

    const int tid  = threadIdx.x;
    const int lane = tid & 31;
    const int warp = tid >> 5;
    const int wm = warp >> 1;   // 0..3  M dir (32 px each)
    const int wn = warp & 1;    // 0..1  N dir (64 och each)
    const int tg = lane & 3;
    const int gp = lane >> 2;

    const int pt  = blockIdx.x * 128;
    const int cid = blockIdx.y >> 1;
    const int ot  = (blockIdx.y & 1) * 128;
    const int bb  = blockIdx.z;

    const float* xb   = x + (size_t)bb * CC * HW;
    const float* wptr = cs.w[cid];
    const float* bptr = cs.b[cid];
    float* out        = cs.out[cid];

    float acc[2][8][4];
#pragma unroll
    for (int mt = 0; mt < 2; ++mt)
#pragma unroll
        for (int nt = 0; nt < 8; ++nt)
#pragma unroll
            for (int i = 0; i < 4; ++i) acc[mt][nt][i] = 0.f;

    for (int kt = 0; kt < CC / 32; ++kt) {
        // ---- X tile: 32 k x 128 p -> Xs[p][kperm] ----
#pragma unroll
        for (int j = 0; j < 4; ++j) {
            int slot = j * 256 + tid;
            int p = slot & 127, q = slot >> 7;
            uint32_t v[4];
#pragma unroll
            for (int r = 0; r < 4; ++r) {
                int kp = q * 4 + r;
                int k = ((kp & 7) << 2) + (kp >> 3);   // inverse of kperm
                v[r] = f2tf32(xb[(size_t)(kt * 32 + k) * HW + pt + p]);
            }
            *reinterpret_cast<uint4*>(&Xs[p * PAD + q * 4]) =
                make_uint4(v[0], v[1], v[2], v[3]);
        }
        // ---- W tile: 128 o x 32 c -> Ws[o][kperm], float4 gmem loads ----
#pragma unroll
        for (int j = 0; j < 4; ++j) {
            int slot = j * 256 + tid;
            int o = slot >> 3, cq = slot & 7;
            float4 wv = *reinterpret_cast<const float4*>(
                wptr + (size_t)(ot + o) * CC + kt * 32 + cq * 4);
            Ws[o * PAD + 0 + cq]  = f2tf32(wv.x);
            Ws[o * PAD + 8 + cq]  = f2tf32(wv.y);
            Ws[o * PAD + 16 + cq] = f2tf32(wv.z);
            Ws[o * PAD + 24 + cq] = f2tf32(wv.w);
        }
        __syncthreads();

#pragma unroll
        for (int h = 0; h < 2; ++h) {               // two halves of kt
            uint4 af[2][2], bf[8];
#pragma unroll
            for (int mt = 0; mt < 2; ++mt) {
                int row = wm * 32 + mt * 16 + gp;
                af[mt][0] = *reinterpret_cast<uint4*>(&Xs[row * PAD + tg * 8 + h * 4]);
                af[mt][1] = *reinterpret_cast<uint4*>(&Xs[(row + 8) * PAD + tg * 8 + h * 4]);
            }
#pragma unroll
            for (int nt = 0; nt < 8; ++nt) {
                int col = wn * 64 + nt * 8 + gp;
                bf[nt] = *reinterpret_cast<uint4*>(&Ws[col * PAD + tg * 8 + h * 4]);
            }
#pragma unroll
            for (int s = 0; s < 2; ++s) {           // k-steps within half
#pragma unroll
                for (int mt = 0; mt < 2; ++mt) {
                    const uint32_t* a0 = reinterpret_cast<const uint32_t*>(&af[mt][0]);
                    const uint32_t* a1 = reinterpret_cast<const uint32_t*>(&af[mt][1]);
                    uint32_t a[4] = {a0[2 * s], a1[2 * s], a0[2 * s + 1], a1[2 * s + 1]};
#pragma unroll
                    for (int nt = 0; nt < 8; ++nt) {
                        const uint32_t* bw = reinterpret_cast<const uint32_t*>(&bf[nt]);
                        uint32_t bq[2] = {bw[2 * s], bw[2 * s + 1]};
                        mma_tf32(acc[mt][nt], a, bq);
                    }
                }
            }
        }
        __syncthreads();
    }

    // ---- epilogue: bias + BHWC store ----
#pragma unroll
    for (int nt = 0; nt < 8; ++nt) {
        int o = ot + wn * 64 + nt * 8 + tg * 2;
        float b0 = __ldg(&bptr[o]);
        float b1 = __ldg(&bptr[o + 1]);
#pragma unroll
        for (int mt = 0; mt < 2; ++mt) {
#pragma unroll
            for (int hr = 0; hr < 2; ++hr) {
                int pg = pt + wm * 32 + mt * 16 + gp + hr * 8;
                float2 r;
                r.x = acc[mt][nt][hr * 2 + 0] + b0;
                r.y = acc[mt][nt][hr * 2 + 1] + b1;
                if (UPS >= 0 && cid == UPS) {
                    int hh = pg >> 6, wc = pg & 63;
                    float* base = out +
                        ((size_t)bb * 16384 + (size_t)(2 * hh) * 128 + 2 * wc) * CC + o;
                    *reinterpret_cast<float2*>(base) = r;
                    *reinterpret_cast<float2*>(base + CC) = r;
                    *reinterpret_cast<float2*>(base + 128 * CC) = r;
                    *reinterpret_cast<float2*>(base + 128 * CC + CC) = r;
                } else {
                    *reinterpret_cast<float2*>(out + ((size_t)bb * HW + pg) * CC + o) = r;
                }
            }
        }
    }
}

// 3x3 stride-2 pad-1 conv, im2col-on-the-fly, same tile machinery.
// grid: (32, 2, B); blockIdx.y = och half.
__global__ __launch_bounds__(256) void conv3x3s2_kernel(
    const float* __restrict__ x, const float* __restrict__ w,
    const float* __restrict__ bias, float* __restrict__ out) {
    __shared__ uint32_t Xs[128 * PAD];
    __shared__ uint32_t Ws[128 * PAD];

    const int tid  = threadIdx.x;
    const int lane = tid & 31;
    const int warp = tid >> 5;
    const int wm = warp >> 1;
    const int wn = warp & 1;
    const int tg = lane & 3;
    const int gp = lane >> 2;

    const int pt = blockIdx.x * 128;     // output pixel tile in 64x64 grid
    const int ot = blockIdx.y * 128;
    const int bb = blockIdx.z;

    const float* xb = x + (size_t)bb * CC * 16384;

    float acc[2][8][4];
#pragma unroll
    for (int mt = 0; mt < 2; ++mt)
#pragma unroll
        for (int nt = 0; nt < 8; ++nt)
#pragma unroll
            for (int i = 0; i < 4; ++i) acc[mt][nt][i] = 0.f;

    for (int kt = 0; kt < CC / 32; ++kt) {
        for (int tap = 0; tap < 9; ++tap) {
            int ti = tap / 3, tj = tap % 3;
            // ---- X gather with zero-pad ----
#pragma unroll
            for (int j = 0; j < 4; ++j) {
                int slot = j * 256 + tid;
                int p = slot & 127, q = slot >> 7;
                int pg = pt + p;
                int oh = pg >> 6, ow = pg & 63;
                int ih = 2 * oh - 1 + ti;
                int iw = 2 * ow - 1 + tj;
                bool ok = (ih >= 0) && (iw >= 0);
                uint32_t v[4];
#pragma unroll
                for (int r = 0; r < 4; ++r) {
                    int kp = q * 4 + r;
                    int k = ((kp & 7) << 2) + (kp >> 3);
                    float f = ok ? xb[(size_t)(kt * 32 + k) * 16384 + ih * 128 + iw] : 0.f;
                    v[r] = f2tf32(f);
                }
                *reinterpret_cast<uint4*>(&Xs[p * PAD + q * 4]) =
                    make_uint4(v[0], v[1], v[2], v[3]);
            }
            // ---- W tile: w[o][c][ti][tj] ----
#pragma unroll
            for (int j = 0; j < 4; ++j) {
                int slot = j * 256 + tid;
                int o = slot >> 3, cq = slot & 7;
#pragma unroll
                for (int i = 0; i < 4; ++i) {
                    int c = kt * 32 + cq * 4 + i;
                    float f = w[((size_t)(ot + o) * CC + c) * 9 + ti * 3 + tj];
                    Ws[o * PAD + i * 8 + cq] = f2tf32(f);
                }
            }
            __syncthreads();

#pragma unroll
            for (int h = 0; h < 2; ++h) {
                uint4 af[2][2], bf[8];
#pragma unroll
                for (int mt = 0; mt < 2; ++mt) {
                    int row = wm * 32 + mt * 16 + gp;
                    af[mt][0] = *reinterpret_cast<uint4*>(&Xs[row * PAD + tg * 8 + h * 4]);
                    af[mt][1] = *reinterpret_cast<uint4*>(&Xs[(row + 8) * PAD + tg * 8 + h * 4]);
                }
#pragma unroll
                for (int nt = 0; nt < 8; ++nt) {
                    int col = wn * 64 + nt * 8 + gp;
                    bf[nt] = *reinterpret_cast<uint4*>(&Ws[col * PAD + tg * 8 + h * 4]);
                }
#pragma unroll
                for (int s = 0; s < 2; ++s) {
#pragma unroll
                    for (int mt = 0; mt < 2; ++mt) {
                        const uint32_t* a0 = reinterpret_cast<const uint32_t*>(&af[mt][0]);
                        const uint32_t* a1 = reinterpret_cast<const uint32_t*>(&af[mt][1]);
                        uint32_t a[4] = {a0[2 * s], a1[2 * s], a0[2 * s + 1], a1[2 * s + 1]};
#pragma unroll
                        for (int nt = 0; nt < 8; ++nt) {
                            const uint32_t* bw = reinterpret_cast<const uint32_t*>(&bf[nt]);
                            uint32_t bq[2] = {bw[2 * s], bw[2 * s + 1]};
                            mma_tf32(acc[mt][nt], a, bq);
                        }
                    }
                }
            }
            __syncthreads();
        }
    }

#pragma unroll
    for (int nt = 0; nt < 8; ++nt) {
        int o = ot + wn * 64 + nt * 8 + tg * 2;
        float b0 = __ldg(&bias[o]);
        float b1 = __ldg(&bias[o + 1]);
#pragma unroll
        for (int mt = 0; mt < 2; ++mt) {
#pragma unroll
            for (int hr = 0; hr < 2; ++hr) {
                int pg = pt + wm * 32 + mt * 16 + gp + hr * 8;
                float2 r;
                r.x = acc[mt][nt][hr * 2 + 0] + b0;
                r.y = acc[mt][nt][hr * 2 + 1] + b1;
                *reinterpret_cast<float2*>(out + ((size_t)bb * 4096 + pg) * CC + o) = r;
            }
        }
    }
}

extern "C" void kernel_launch(void* const* d_in, const int* in_sizes, int n_in,
                              void* d_out, int out_size) {
    const float* x1 = (const float*)d_in[0];
    const float* x2 = (const float*)d_in[1];
    const float* q1_w = (const float*)d_in[2];
    const float* q1_b = (const float*)d_in[3];
    const float* q2_w = (const float*)d_in[4];
    const float* q2_b = (const float*)d_in[5];
    const float* ks1_w = (const float*)d_in[6];
    const float* ks1_b = (const float*)d_in[7];
    const float* ks2_w = (const float*)d_in[8];
    const float* ks2_b = (const float*)d_in[9];
    const float* kup_w = (const float*)d_in[10];
    const float* kup_b = (const float*)d_in[11];
    const float* v1_w = (const float*)d_in[12];
    const float* v1_b = (const float*)d_in[13];
    const float* v2_w = (const float*)d_in[14];
    const float* v2_b = (const float*)d_in[15];
    const float* kd_w = (const float*)d_in[16];
    const float* kd_b = (const float*)d_in[17];

    float* out = (float*)d_out;
    float* q1  = out;                    // 2*128*128*256
    float* q2  = out + 8388608;          // 2*64*64*256
    float* kup = out + 10485760;         // 2*128*128*256 (upsampled)
    float* ks1 = out + 18874368;
    float* ks2 = out + 27262976;
    float* kdn = out + 29360128;
    float* v1  = out + 31457280;
    float* v2  = out + 39845888;

    ConvSet cs1;
    cs1.w[0] = q1_w;  cs1.b[0] = q1_b;  cs1.out[0] = q1;
    cs1.w[1] = ks1_w; cs1.b[1] = ks1_b; cs1.out[1] = ks1;
    cs1.w[2] = v1_w;  cs1.b[2] = v1_b;  cs1.out[2] = v1;
    cs1.w[3] = q1_w;  cs1.b[3] = q1_b;  cs1.out[3] = q1;  // unused

    ConvSet cs2;
    cs2.w[0] = q2_w;  cs2.b[0] = q2_b;  cs2.out[0] = q2;
    cs2.w[1] = ks2_w; cs2.b[1] = ks2_b; cs2.out[1] = ks2;
    cs2.w[2] = v2_w;  cs2.b[2] = v2_b;  cs2.out[2] = v2;
    cs2.w[3] = kup_w; cs2.b[3] = kup_b; cs2.out[3] = kup;

    dim3 blk(256);
    conv1x1_fused<-1><<<dim3(128, 6, 2), blk>>>(x1, cs1, 16384);
    conv1x1_fused<3><<<dim3(32, 8, 2), blk>>>(x2, cs2, 4096);
    conv3x3s2_kernel<<<dim3(32, 2, 2), blk>>>(x1, kd_w, kd_b, kdn);
}